// round 8
// baseline (speedup 1.0000x reference)
#include <cuda_runtime.h>
#include <math.h>

#define NH   64
#define NI   128
#define NHID 512
#define NO   256
#define NS   4

// Block-role layout: homogeneous w2 blocks first (self-sufficient streamers)
#define B_W2   512                   // 8 per head: compute w1 slice + w2 chunk
#define B_WS   128                   // ws row-sums
#define B_EPI  64
#define OFF_WS (B_W2)                // 512
#define OFF_EPI (B_W2 + B_WS)        // 640
#define NBLK   (OFF_EPI + B_EPI)     // 704

#define CNTB_TARGET 8u               // 8 w1 slices per head
#define CNT_TARGET  10u              // 8 w2 chunks + 2 ws blocks per head

// Scratch (device globals)
__device__ float g_z1[NH * NHID];
__device__ float g_z[NS * NH * NO];
__device__ float g_scalar[NH * NO];
__device__ unsigned g_cntb[NH];
__device__ unsigned g_cnt[NH];

__device__ __forceinline__ float dot4(float4 a, float4 b) {
    return a.x * b.x + a.y * b.y + a.z * b.z + a.w * b.w;
}

__device__ __forceinline__ float warp_sum(float v) {
#pragma unroll
    for (int o = 16; o; o >>= 1) v += __shfl_xor_sync(0xffffffffu, v, o);
    return v;
}

// Reduce 8 per-thread accumulators across the warp in 9 shuffles.
// Returns full sum of row (lane & 7).
__device__ __forceinline__ float reduce8(const float acc[8], int lane) {
    float a[4], b[2], c;
#pragma unroll
    for (int i = 0; i < 4; i++) {
        float keep = (lane & 1) ? acc[2 * i + 1] : acc[2 * i];
        float send = (lane & 1) ? acc[2 * i]     : acc[2 * i + 1];
        a[i] = keep + __shfl_xor_sync(0xffffffffu, send, 1);
    }
#pragma unroll
    for (int i = 0; i < 2; i++) {
        float keep = (lane & 2) ? a[2 * i + 1] : a[2 * i];
        float send = (lane & 2) ? a[2 * i]     : a[2 * i + 1];
        b[i] = keep + __shfl_xor_sync(0xffffffffu, send, 2);
    }
    {
        float keep = (lane & 4) ? b[1] : b[0];
        float send = (lane & 4) ? b[0] : b[1];
        c = keep + __shfl_xor_sync(0xffffffffu, send, 4);
    }
    c += __shfl_xor_sync(0xffffffffu, c, 8);
    c += __shfl_xor_sync(0xffffffffu, c, 16);
    return c;
}

// Reduce 4 per-thread accumulators: 6 shuffles; returns sum of row (lane & 3).
__device__ __forceinline__ float reduce4(const float acc[4], int lane) {
    float a[2], c;
#pragma unroll
    for (int i = 0; i < 2; i++) {
        float keep = (lane & 1) ? acc[2 * i + 1] : acc[2 * i];
        float send = (lane & 1) ? acc[2 * i]     : acc[2 * i + 1];
        a[i] = keep + __shfl_xor_sync(0xffffffffu, send, 1);
    }
    {
        float keep = (lane & 2) ? a[1] : a[0];
        float send = (lane & 2) ? a[0] : a[1];
        c = keep + __shfl_xor_sync(0xffffffffu, send, 2);
    }
    c += __shfl_xor_sync(0xffffffffu, c, 4);
    c += __shfl_xor_sync(0xffffffffu, c, 8);
    c += __shfl_xor_sync(0xffffffffu, c, 16);
    return c;
}

__device__ __forceinline__ unsigned ld_acq(const unsigned* p) {
    unsigned v;
    asm volatile("ld.acquire.gpu.u32 %0, [%1];" : "=r"(v) : "l"(p) : "memory");
    return v;
}

// ---------------------------------------------------------------------------
__global__ void __launch_bounds__(512, 2) k_main(
    const float* __restrict__ x,   const float* __restrict__ qw,
    const float* __restrict__ w1,  const float* __restrict__ g1,
    const float* __restrict__ b1,  const float* __restrict__ w2,
    const float* __restrict__ g2,  const float* __restrict__ b2,
    const float* __restrict__ ws,  const float* __restrict__ last,
    const float* __restrict__ woo, float* __restrict__ out)
{
    const int bid = blockIdx.x;
    const int tid = threadIdx.x, warp = tid >> 5, lane = tid & 31;

    // ====== w2 blocks [0,512): sub + own w1 slice + sibling-wait + GN + w2 =
    if (bid < B_W2) {
        const int h = bid >> 3, sib = bid & 7;
        const int s = sib >> 1, chunk = sib & 1;
        __shared__ float s_qw[NI];
        __shared__ float s_sub[NI];
        __shared__ float s_h1s[NHID];
        __shared__ float red[32];

        if (tid < NI) s_qw[tid] = qw[h * NI + tid];
        __syncthreads();

        {   // sub[r] = x[r,:] . qw[h]  — 8 rows/warp, x is L2-hot
            float4 qv = ((const float4*)s_qw)[lane];
            float part[8];
#pragma unroll
            for (int rr = 0; rr < 8; rr++) {
                const int r = warp * 8 + rr;
                float4 xv = ((const float4*)(x + (size_t)r * NI))[lane];
                part[rr] = dot4(xv, qv);
            }
            float c = reduce8(part, lane);
            if (lane < 8) s_sub[warp * 8 + lane] = c;
        }
        __syncthreads();

        {   // own w1 slice: 64 rows (4 rows/warp), write z1, bump counter
            const int row0 = sib * 64 + warp * 4;
            const float* w1b = w1 + ((size_t)h * NHID + row0) * NI;
            float4 sv = ((const float4*)s_sub)[lane];
            float acc[4];
#pragma unroll
            for (int rr = 0; rr < 4; rr++) {
                float4 wv = __ldcs(((const float4*)(w1b + (size_t)rr * NI)) + lane);
                acc[rr] = dot4(wv, sv);
            }
            float c = reduce4(acc, lane);
            if (lane < 4) g_z1[(size_t)h * NHID + row0 + lane] = c;
        }
        __syncthreads();
        if (tid == 0) {
            __threadfence();
            atomicAdd(&g_cntb[h], 1u);
            while (ld_acq(&g_cntb[h]) < CNTB_TARGET) __nanosleep(32);
        }
        __syncthreads();

        {   // inline GroupNorm + softplus (z1 is L2-hot)
            float v = g_z1[(size_t)h * NHID + tid];
            float s1 = warp_sum(v);
            float s2 = warp_sum(v * v);
            if (lane == 0) { red[warp] = s1; red[16 + warp] = s2; }
            __syncthreads();
            float sum = 0.f, sqs = 0.f;
#pragma unroll
            for (int j = 0; j < 16; j++) { sum += red[j]; sqs += red[16 + j]; }
            float mean = sum * (1.f / NHID);
            float var  = sqs * (1.f / NHID) - mean * mean;
            float zn = (v - mean) * rsqrtf(var + 1e-5f) * g1[h * NHID + tid]
                     + b1[h * NHID + tid];
            s_h1s[tid] = fmaxf(zn, 0.f) + log1pf(expf(-fabsf(zn)));
        }
        __syncthreads();

        // w2 chunk: 128 rows of 512, 8 rows/warp
        const int row0 = chunk * 128 + warp * 8;
        const float* wb = w2 + ((size_t)((s * NH + h) * NO) + row0) * NHID;
        const float4* hv4 = (const float4*)s_h1s;

        float acc[8] = {0.f, 0.f, 0.f, 0.f, 0.f, 0.f, 0.f, 0.f};
#pragma unroll
        for (int c = 0; c < 4; c++) {
            float4 hv = hv4[lane + c * 32];
#pragma unroll
            for (int rr = 0; rr < 8; rr++) {
                float4 wv = __ldcs(((const float4*)(wb + (size_t)rr * NHID)) + lane + c * 32);
                acc[rr] += dot4(wv, hv);
            }
        }
        float c = reduce8(acc, lane);
        if (lane < 8)
            g_z[(size_t)(s * NH + h) * NO + row0 + lane] = c;
        __syncthreads();
        if (tid == 0) { __threadfence(); atomicAdd(&g_cnt[h], 1u); }
        return;
    }

    // ============ ws blocks [512,640): row sums, 8 rows/warp ===============
    if (bid < OFF_EPI) {
        const int wsb = bid - OFF_WS;
        const int rowbase = wsb * 128 + warp * 8;
        float acc[8];
#pragma unroll
        for (int rr = 0; rr < 8; rr++) {
            const float4* r = (const float4*)(ws + (size_t)(rowbase + rr) * NO);
            float4 a = __ldcs(r + lane), b = __ldcs(r + lane + 32);
            acc[rr] = a.x + a.y + a.z + a.w + b.x + b.y + b.z + b.w;
        }
        float c = reduce8(acc, lane);
        if (lane < 8) g_scalar[rowbase + lane] = c;
        __syncthreads();
        if (tid == 0) { __threadfence(); atomicAdd(&g_cnt[wsb >> 1], 1u); }
        return;
    }

    // ============ epilogue blocks [640,704) ================================
    {
        const int h = bid - OFF_EPI;
        __shared__ float s_z[NS * NO];
        __shared__ float s_lp[NO];
        __shared__ float rsum[16], rsq[16], rmax[16], resum[16], redg[16];

        // last_prod (coalesced; overlaps the wait)
#pragma unroll
        for (int k = 0; k < 16; k++) {
            const int o = k * 16 + warp;
            float v = last[o * NH + lane] * last[o * NH + 32 + lane];
#pragma unroll
            for (int m = 16; m; m >>= 1) v *= __shfl_xor_sync(0xffffffffu, v, m);
            if (lane == 0) s_lp[o] = v;
        }

        if (tid == 0) { while (ld_acq(&g_cnt[h]) != CNT_TARGET) __nanosleep(128); }
        __syncthreads();

        for (int i = tid; i < NS * NO; i += 512) {
            const int s = i >> 8, o = i & 255;
            s_z[i] = g_z[(size_t)(s * NH + h) * NO + o];
        }
        __syncthreads();

        // 4 GroupNorm+softmax, two 256-thread groups per pass
#pragma unroll
        for (int pass = 0; pass < 2; pass++) {
            const int grp = tid >> 8;
            const int s = pass * 2 + grp;
            const int o = tid & 255;
            const int wg = (tid >> 5) & 7;

            float v = s_z[s * NO + o];
            float su = warp_sum(v);
            float sq = warp_sum(v * v);
            if (lane == 0) { rsum[grp * 8 + wg] = su; rsq[grp * 8 + wg] = sq; }
            __syncthreads();
            float sum = 0.f, sqs = 0.f;
#pragma unroll
            for (int j = 0; j < 8; j++) { sum += rsum[grp * 8 + j]; sqs += rsq[grp * 8 + j]; }
            float mean = sum * (1.f / NO);
            float var  = sqs * (1.f / NO) - mean * mean;
            const int gidx = (s * NH + h) * NO + o;
            float zn = (v - mean) * rsqrtf(var + 1e-5f) * g2[gidx] + b2[gidx];

            float mx = zn;
#pragma unroll
            for (int m = 16; m; m >>= 1) mx = fmaxf(mx, __shfl_xor_sync(0xffffffffu, mx, m));
            if (lane == 0) rmax[grp * 8 + wg] = mx;
            __syncthreads();
            float M = -INFINITY;
#pragma unroll
            for (int j = 0; j < 8; j++) M = fmaxf(M, rmax[grp * 8 + j]);

            float e = expf(zn - M);
            float se = warp_sum(e);
            if (lane == 0) resum[grp * 8 + wg] = se;
            __syncthreads();
            float es = 0.f;
#pragma unroll
            for (int j = 0; j < 8; j++) es += resum[grp * 8 + j];
            s_z[s * NO + o] = e / es;
            __syncthreads();
        }

        const int o = tid;
        float osm = 0.f, part = 0.f;
        if (tid < NO) {
            osm = s_z[o] + s_z[NO + o] + s_z[2 * NO + o] + s_z[3 * NO + o];
            part = woo[h * 2 * NO + o] * s_lp[o] + woo[h * 2 * NO + NO + o] * osm;
        }
        float ps = warp_sum(part);
        if (lane == 0) redg[warp] = ps;
        __syncthreads();
        float gl = 0.f;
#pragma unroll
        for (int j = 0; j < 16; j++) gl += redg[j];
        float onoff = 1.f / (1.f + expf(-gl));

        if (tid < NO) {
            float oo = onoff * osm;
            float out0 = fmaxf(oo, 1e-14f);
            float sc = g_scalar[h * NO + o];
            float raw = oo * sc;
            float out1 = (fabsf(raw) <= 1e-14f) ? 1e-14f : raw;
            out[o * NH + h] = out0;
            out[NO * NH + o * NH + h] = out1;
        }
        __syncthreads();
        if (tid == 0) { g_cnt[h] = 0u; g_cntb[h] = 0u; }   // reset for next replay
    }
}

// ---------------------------------------------------------------------------
extern "C" void kernel_launch(void* const* d_in, const int* in_sizes, int n_in,
                              void* d_out, int out_size)
{
    const float* x    = (const float*)d_in[0];
    const float* last = (const float*)d_in[1];
    const float* qw   = (const float*)d_in[2];
    const float* w1   = (const float*)d_in[3];
    const float* g1   = (const float*)d_in[4];
    const float* b1   = (const float*)d_in[5];
    const float* w2   = (const float*)d_in[6];
    const float* g2   = (const float*)d_in[7];
    const float* b2   = (const float*)d_in[8];
    const float* ws   = (const float*)d_in[9];
    const float* woo  = (const float*)d_in[10];
    float* out = (float*)d_out;

    k_main<<<NBLK, 512>>>(x, qw, w1, g1, b1, w2, g2, b2, ws, last, woo, out);
}

// round 9
// speedup vs baseline: 1.1388x; 1.1388x over previous
#include <cuda_runtime.h>
#include <math.h>

#define NH   64
#define NI   128
#define NHID 512
#define NO   256
#define NS   4

#define B_W1 128                     // 2 per head, 256 w1 rows each
#define B_W2 512                     // 8 per head (4 s x 2 chunks of 128 rows)
#define NBLK (B_W1 + B_W2)           // 640

#define CNTB_TARGET 2u               // 2 w1 halves per head
#define CNT_TARGET  8u               // 8 w2 siblings per head

// Scratch (device globals)
__device__ float g_z1[NH * NHID];
__device__ float g_z[NS * NH * NO];
__device__ float g_scalar[NH * NO];
__device__ float g_lp[NO];
__device__ unsigned g_cntb[NH];
__device__ unsigned g_cnt[NH];

__device__ __forceinline__ float dot4(float4 a, float4 b) {
    return a.x * b.x + a.y * b.y + a.z * b.z + a.w * b.w;
}

__device__ __forceinline__ float warp_sum(float v) {
#pragma unroll
    for (int o = 16; o; o >>= 1) v += __shfl_xor_sync(0xffffffffu, v, o);
    return v;
}

// Reduce 8 per-thread accumulators across the warp in 9 shuffles.
// Returns full sum of row (lane & 7).
__device__ __forceinline__ float reduce8(const float acc[8], int lane) {
    float a[4], b[2], c;
#pragma unroll
    for (int i = 0; i < 4; i++) {
        float keep = (lane & 1) ? acc[2 * i + 1] : acc[2 * i];
        float send = (lane & 1) ? acc[2 * i]     : acc[2 * i + 1];
        a[i] = keep + __shfl_xor_sync(0xffffffffu, send, 1);
    }
#pragma unroll
    for (int i = 0; i < 2; i++) {
        float keep = (lane & 2) ? a[2 * i + 1] : a[2 * i];
        float send = (lane & 2) ? a[2 * i]     : a[2 * i + 1];
        b[i] = keep + __shfl_xor_sync(0xffffffffu, send, 2);
    }
    {
        float keep = (lane & 4) ? b[1] : b[0];
        float send = (lane & 4) ? b[0] : b[1];
        c = keep + __shfl_xor_sync(0xffffffffu, send, 4);
    }
    c += __shfl_xor_sync(0xffffffffu, c, 8);
    c += __shfl_xor_sync(0xffffffffu, c, 16);
    return c;
}

// 2-row combine (sum): returns full sum of row (lane & 1) in 5 shuffles.
__device__ __forceinline__ float reduce2_sum(float s0, float s1, int lane) {
    float keep = (lane & 1) ? s1 : s0;
    float send = (lane & 1) ? s0 : s1;
    float c = keep + __shfl_xor_sync(0xffffffffu, send, 1);
    c += __shfl_xor_sync(0xffffffffu, c, 2);
    c += __shfl_xor_sync(0xffffffffu, c, 4);
    c += __shfl_xor_sync(0xffffffffu, c, 8);
    c += __shfl_xor_sync(0xffffffffu, c, 16);
    return c;
}

// 2-row combine (product): returns full product of row (lane & 1).
__device__ __forceinline__ float reduce2_prod(float s0, float s1, int lane) {
    float keep = (lane & 1) ? s1 : s0;
    float send = (lane & 1) ? s0 : s1;
    float c = keep * __shfl_xor_sync(0xffffffffu, send, 1);
    c *= __shfl_xor_sync(0xffffffffu, c, 2);
    c *= __shfl_xor_sync(0xffffffffu, c, 4);
    c *= __shfl_xor_sync(0xffffffffu, c, 8);
    c *= __shfl_xor_sync(0xffffffffu, c, 16);
    return c;
}

__device__ __forceinline__ unsigned ld_acq(const unsigned* p) {
    unsigned v;
    asm volatile("ld.acquire.gpu.u32 %0, [%1];" : "=r"(v) : "l"(p) : "memory");
    return v;
}

// ---------------------------------------------------------------------------
__global__ void __launch_bounds__(512, 2) k_main(
    const float* __restrict__ x,   const float* __restrict__ qw,
    const float* __restrict__ w1,  const float* __restrict__ g1,
    const float* __restrict__ b1,  const float* __restrict__ w2,
    const float* __restrict__ g2,  const float* __restrict__ b2,
    const float* __restrict__ ws,  const float* __restrict__ last,
    const float* __restrict__ woo, float* __restrict__ out)
{
    const int bid = blockIdx.x;
    const int tid = threadIdx.x, warp = tid >> 5, lane = tid & 31;

    // ============ w1 blocks [0,128): sub (redundant x2) + 256 w1 rows ======
    if (bid < B_W1) {
        const int h = bid >> 1, q = bid & 1;
        __shared__ float s_qw[NI];
        __shared__ float s_sub[NI];

        if (tid < NI) s_qw[tid] = qw[h * NI + tid];
        __syncthreads();

        {   // sub[r] = x[r,:] . qw[h]  — 8 rows/warp, x is L2-hot
            float4 qv = ((const float4*)s_qw)[lane];
            float part[8];
#pragma unroll
            for (int rr = 0; rr < 8; rr++) {
                const int r = warp * 8 + rr;
                float4 xv = ((const float4*)(x + (size_t)r * NI))[lane];
                part[rr] = dot4(xv, qv);
            }
            float c = reduce8(part, lane);
            if (lane < 8) s_sub[warp * 8 + lane] = c;
        }
        __syncthreads();

        {   // w1 half: 256 rows, 16 rows/warp in two groups of 8
            const int row0 = q * 256 + warp * 16;
            const float* w1b = w1 + ((size_t)h * NHID + row0) * NI;
            float4 sv = ((const float4*)s_sub)[lane];
#pragma unroll
            for (int g = 0; g < 2; g++) {
                float acc[8];
#pragma unroll
                for (int rr = 0; rr < 8; rr++) {
                    float4 wv = __ldcs(((const float4*)(w1b + (size_t)(g * 8 + rr) * NI)) + lane);
                    acc[rr] = dot4(wv, sv);
                }
                float c = reduce8(acc, lane);
                if (lane < 8) g_z1[(size_t)h * NHID + row0 + g * 8 + lane] = c;
            }
        }
        __syncthreads();
        if (tid == 0) { __threadfence(); atomicAdd(&g_cntb[h], 1u); }
        return;
    }

    // ====== w2 blocks [128,640): lp + ws slices, prefetch, wait, GN, w2 ====
    {
        const int b2i = bid - B_W1;             // 0..511
        const int h = b2i >> 3, sib = b2i & 7;
        const int s = sib >> 1, chunk = sib & 1;
        __shared__ float s_h1s[NHID];
        __shared__ float red[32];
        __shared__ float s_z[NS * NO];
        __shared__ float rsum[16], rsq[16], rmax[16], resum[16], redg[16];
        __shared__ unsigned s_ready, s_old;

        const float* wb = w2 + ((size_t)((s * NH + h) * NO) + chunk * 128) * NHID;

        // ---- lp slice: 32 rows of last_prod (redundant across heads, benign)
        {
            const int o0 = sib * 32 + warp * 2;
            float v0 = last[o0 * NH + lane] * last[o0 * NH + 32 + lane];
            float v1 = last[(o0 + 1) * NH + lane] * last[(o0 + 1) * NH + 32 + lane];
            float c = reduce2_prod(v0, v1, lane);
            if (lane < 2) g_lp[o0 + lane] = c;
        }

        // ---- ws slice: 32 rows of this head's ws (streams during phase 1)
        {
            const int rowbase = h * NO + sib * 32 + warp * 2;
            const float4* r0 = (const float4*)(ws + (size_t)rowbase * NO);
            const float4* r1 = (const float4*)(ws + (size_t)(rowbase + 1) * NO);
            float4 a0 = __ldcs(r0 + lane), b0 = __ldcs(r0 + lane + 32);
            float4 a1 = __ldcs(r1 + lane), b1_ = __ldcs(r1 + lane + 32);
            float s0 = a0.x + a0.y + a0.z + a0.w + b0.x + b0.y + b0.z + b0.w;
            float s1 = a1.x + a1.y + a1.z + a1.w + b1_.x + b1_.y + b1_.z + b1_.w;
            float c = reduce2_sum(s0, s1, lane);
            if (lane < 2) g_scalar[rowbase - h * NO + h * NO + lane] = c;  // = g_scalar[rowbase+lane]
        }

        // ---- if h1 not ready yet (phase 1), prefetch our w2 chunk into L2
        if (tid == 0) s_ready = ld_acq(&g_cntb[h]);
        __syncthreads();
        if (s_ready < CNTB_TARGET) {
            const char* base = (const char*)wb;
#pragma unroll
            for (int i = 0; i < 4; i++) {
                const char* p = base + ((size_t)tid + (size_t)i * 512) * 128;
                asm volatile("prefetch.global.L2 [%0];" :: "l"(p));
            }
        }

        // ---- wait for this head's w1
        if (tid == 0) { while (ld_acq(&g_cntb[h]) < CNTB_TARGET) __nanosleep(32); }
        __syncthreads();

        // ---- inline GroupNorm + softplus (z1 is L2-hot)
        {
            float v = g_z1[(size_t)h * NHID + tid];
            float s1r = warp_sum(v);
            float s2r = warp_sum(v * v);
            if (lane == 0) { red[warp] = s1r; red[16 + warp] = s2r; }
            __syncthreads();
            float sum = 0.f, sqs = 0.f;
#pragma unroll
            for (int j = 0; j < 16; j++) { sum += red[j]; sqs += red[16 + j]; }
            float mean = sum * (1.f / NHID);
            float var  = sqs * (1.f / NHID) - mean * mean;
            float zn = (v - mean) * rsqrtf(var + 1e-5f) * g1[h * NHID + tid]
                     + b1[h * NHID + tid];
            s_h1s[tid] = fmaxf(zn, 0.f) + log1pf(expf(-fabsf(zn)));
        }
        __syncthreads();

        // ---- w2 chunk: 128 rows of 512, 8 rows/warp
        const int row0 = chunk * 128 + warp * 8;
        const float* wbr = wb + (size_t)(warp * 8) * NHID;
        const float4* hv4 = (const float4*)s_h1s;

        float acc[8] = {0.f, 0.f, 0.f, 0.f, 0.f, 0.f, 0.f, 0.f};
#pragma unroll
        for (int c = 0; c < 4; c++) {
            float4 hv = hv4[lane + c * 32];
#pragma unroll
            for (int rr = 0; rr < 8; rr++) {
                float4 wv = __ldcs(((const float4*)(wbr + (size_t)rr * NHID)) + lane + c * 32);
                acc[rr] += dot4(wv, hv);
            }
        }
        float c = reduce8(acc, lane);
        if (lane < 8)
            g_z[(size_t)(s * NH + h) * NO + row0 + lane] = c;

        // ---- bump; last finisher does the epilogue inline
        __syncthreads();
        if (tid == 0) {
            __threadfence();
            s_old = atomicAdd(&g_cnt[h], 1u);
            if (s_old == CNT_TARGET - 1) __threadfence();
        }
        __syncthreads();
        if (s_old != CNT_TARGET - 1) return;

        // ================= epilogue (finisher only) ========================
        for (int i = tid; i < NS * NO; i += 512) {
            const int ss = i >> 8, o = i & 255;
            s_z[i] = g_z[(size_t)(ss * NH + h) * NO + o];
        }
        __syncthreads();

        // 4 GroupNorm+softmax, two 256-thread groups per pass
#pragma unroll
        for (int pass = 0; pass < 2; pass++) {
            const int grp = tid >> 8;
            const int ss = pass * 2 + grp;
            const int o = tid & 255;
            const int wg = (tid >> 5) & 7;

            float v = s_z[ss * NO + o];
            float su = warp_sum(v);
            float sq = warp_sum(v * v);
            if (lane == 0) { rsum[grp * 8 + wg] = su; rsq[grp * 8 + wg] = sq; }
            __syncthreads();
            float sum = 0.f, sqs = 0.f;
#pragma unroll
            for (int j = 0; j < 8; j++) { sum += rsum[grp * 8 + j]; sqs += rsq[grp * 8 + j]; }
            float mean = sum * (1.f / NO);
            float var  = sqs * (1.f / NO) - mean * mean;
            const int gidx = (ss * NH + h) * NO + o;
            float zn = (v - mean) * rsqrtf(var + 1e-5f) * g2[gidx] + b2[gidx];

            float mx = zn;
#pragma unroll
            for (int m = 16; m; m >>= 1) mx = fmaxf(mx, __shfl_xor_sync(0xffffffffu, mx, m));
            if (lane == 0) rmax[grp * 8 + wg] = mx;
            __syncthreads();
            float M = -INFINITY;
#pragma unroll
            for (int j = 0; j < 8; j++) M = fmaxf(M, rmax[grp * 8 + j]);

            float e = expf(zn - M);
            float se = warp_sum(e);
            if (lane == 0) resum[grp * 8 + wg] = se;
            __syncthreads();
            float es = 0.f;
#pragma unroll
            for (int j = 0; j < 8; j++) es += resum[grp * 8 + j];
            s_z[ss * NO + o] = e / es;
            __syncthreads();
        }

        const int o = tid;
        float osm = 0.f, part = 0.f;
        if (tid < NO) {
            osm = s_z[o] + s_z[NO + o] + s_z[2 * NO + o] + s_z[3 * NO + o];
            part = woo[h * 2 * NO + o] * g_lp[o] + woo[h * 2 * NO + NO + o] * osm;
        }
        float ps = warp_sum(part);
        if (lane == 0) redg[warp] = ps;
        __syncthreads();
        float gl = 0.f;
#pragma unroll
        for (int j = 0; j < 16; j++) gl += redg[j];
        float onoff = 1.f / (1.f + expf(-gl));

        if (tid < NO) {
            float oo = onoff * osm;
            float out0 = fmaxf(oo, 1e-14f);
            float sc = g_scalar[h * NO + o];
            float raw = oo * sc;
            float out1 = (fabsf(raw) <= 1e-14f) ? 1e-14f : raw;
            out[o * NH + h] = out0;
            out[NO * NH + o * NH + h] = out1;
        }
        __syncthreads();
        if (tid == 0) { g_cnt[h] = 0u; g_cntb[h] = 0u; }   // reset for next replay
    }
}

// ---------------------------------------------------------------------------
extern "C" void kernel_launch(void* const* d_in, const int* in_sizes, int n_in,
                              void* d_out, int out_size)
{
    const float* x    = (const float*)d_in[0];
    const float* last = (const float*)d_in[1];
    const float* qw   = (const float*)d_in[2];
    const float* w1   = (const float*)d_in[3];
    const float* g1   = (const float*)d_in[4];
    const float* b1   = (const float*)d_in[5];
    const float* w2   = (const float*)d_in[6];
    const float* g2   = (const float*)d_in[7];
    const float* b2   = (const float*)d_in[8];
    const float* ws   = (const float*)d_in[9];
    const float* woo  = (const float*)d_in[10];
    float* out = (float*)d_out;

    k_main<<<NBLK, 512>>>(x, qw, w1, g1, b1, w2, g2, b2, ws, last, woo, out);
}